// round 12
// baseline (speedup 1.0000x reference)
#include <cuda_runtime.h>

// Per-row L2 normalization: out[r,:] = in[r,:] * rsqrt(sum(in[r,:]^2))
// 16384 rows x 4096 cols fp32. Two rows per 512-thread CTA (grid 8192):
// all 4 row-loads issued up front (batched READ burst), both rows reduced
// with ONE barrier (two smem arrays), then all 4 stores back-to-back
// (batched WRITE burst) — longer same-direction DRAM runs, fewer bus
// turnarounds, half the barriers per byte. Streaming .cs on both paths.

#define ROWS 16384
#define VEC_PER_ROW 1024             // 4096 floats / 4
#define THREADS 512
#define VPT 2                        // float4 per thread per row
#define ROWS_PER_CTA 2
#define NWARPS (THREADS / 32)        // 16

__global__ __launch_bounds__(THREADS, 3)
void l2norm_row2_kernel(const float4* __restrict__ in, float4* __restrict__ out) {
    const int row0 = blockIdx.x * ROWS_PER_CTA;
    const size_t base0 = (size_t)row0 * VEC_PER_ROW;
    const size_t base1 = base0 + VEC_PER_ROW;
    const int t = threadIdx.x;

    // Batched read burst: 4 independent LDG.128.CS (2 per row).
    float4 a[VPT], b[VPT];
#pragma unroll
    for (int i = 0; i < VPT; i++) a[i] = __ldcs(&in[base0 + t + i * THREADS]);
#pragma unroll
    for (int i = 0; i < VPT; i++) b[i] = __ldcs(&in[base1 + t + i * THREADS]);

    // Per-thread sums of squares for both rows.
    float sa = 0.0f, sb = 0.0f;
#pragma unroll
    for (int i = 0; i < VPT; i++) {
        sa = fmaf(a[i].x, a[i].x, sa);
        sa = fmaf(a[i].y, a[i].y, sa);
        sa = fmaf(a[i].z, a[i].z, sa);
        sa = fmaf(a[i].w, a[i].w, sa);
        sb = fmaf(b[i].x, b[i].x, sb);
        sb = fmaf(b[i].y, b[i].y, sb);
        sb = fmaf(b[i].z, b[i].z, sb);
        sb = fmaf(b[i].w, b[i].w, sb);
    }

    // Warp reduce both rows.
#pragma unroll
    for (int o = 16; o > 0; o >>= 1) {
        sa += __shfl_xor_sync(0xffffffffu, sa, o);
        sb += __shfl_xor_sync(0xffffffffu, sb, o);
    }

    // Cross-warp combine for both rows, ONE barrier.
    __shared__ float wsum_a[NWARPS];
    __shared__ float wsum_b[NWARPS];
    if ((t & 31) == 0) {
        wsum_a[t >> 5] = sa;
        wsum_b[t >> 5] = sb;
    }
    __syncthreads();

    float ta = 0.0f, tb = 0.0f;
#pragma unroll
    for (int w = 0; w < NWARPS; w++) {
        ta += wsum_a[w];
        tb += wsum_b[w];
    }

    const float inva = rsqrtf(ta);
    const float invb = rsqrtf(tb);

    // Batched write burst: 4 STG.128.CS back-to-back.
#pragma unroll
    for (int i = 0; i < VPT; i++) {
        float4 o4;
        o4.x = a[i].x * inva;
        o4.y = a[i].y * inva;
        o4.z = a[i].z * inva;
        o4.w = a[i].w * inva;
        __stcs(&out[base0 + t + i * THREADS], o4);
    }
#pragma unroll
    for (int i = 0; i < VPT; i++) {
        float4 o4;
        o4.x = b[i].x * invb;
        o4.y = b[i].y * invb;
        o4.z = b[i].z * invb;
        o4.w = b[i].w * invb;
        __stcs(&out[base1 + t + i * THREADS], o4);
    }
}

extern "C" void kernel_launch(void* const* d_in, const int* in_sizes, int n_in,
                              void* d_out, int out_size) {
    const float4* in = (const float4*)d_in[0];
    float4* out = (float4*)d_out;
    l2norm_row2_kernel<<<ROWS / ROWS_PER_CTA, THREADS>>>(in, out);
}

// round 13
// speedup vs baseline: 1.0260x; 1.0260x over previous
#include <cuda_runtime.h>

// Per-row L2 normalization: out[r,:] = in[r,:] * rsqrt(sum(in[r,:]^2))
// 16384 rows x 4096 cols fp32. 512-thread CTA per row; each thread moves the
// row with ONE 256-bit vector load and ONE 256-bit vector store
// (Blackwell LDG.E.256 / STG.E.256, PTX v8.f32 — sm_100a+ only).
// MLP_p1 = 1 (cross-CTA L1tex spread floor) with a full row in flight per
// CTA from a single issue slot per thread. Streaming .cs on both paths.

#define ROWS 16384
#define THREADS 512
#define FLOATS_PER_ROW 4096
#define F_PER_THREAD 8              // 8 floats = 32 bytes = one 256-bit op

__device__ __forceinline__ void ld256_cs(const float* p, float* r) {
    asm volatile(
        "ld.global.cs.v8.f32 {%0,%1,%2,%3,%4,%5,%6,%7}, [%8];"
        : "=f"(r[0]), "=f"(r[1]), "=f"(r[2]), "=f"(r[3]),
          "=f"(r[4]), "=f"(r[5]), "=f"(r[6]), "=f"(r[7])
        : "l"(p));
}

__device__ __forceinline__ void st256_cs(float* p, const float* r) {
    asm volatile(
        "st.global.cs.v8.f32 [%0], {%1,%2,%3,%4,%5,%6,%7,%8};"
        :: "l"(p),
           "f"(r[0]), "f"(r[1]), "f"(r[2]), "f"(r[3]),
           "f"(r[4]), "f"(r[5]), "f"(r[6]), "f"(r[7])
        : "memory");
}

__global__ __launch_bounds__(THREADS, 4)
void l2norm_row256b_kernel(const float* __restrict__ in, float* __restrict__ out) {
    const int row = blockIdx.x;
    const int t = threadIdx.x;
    const size_t off = (size_t)row * FLOATS_PER_ROW + (size_t)t * F_PER_THREAD;

    // One 256-bit streaming load per thread: whole row in flight per CTA.
    float v[F_PER_THREAD];
    ld256_cs(in + off, v);

    // Per-thread sum of squares over 8 values.
    float ss = 0.0f;
#pragma unroll
    for (int i = 0; i < F_PER_THREAD; i++) ss = fmaf(v[i], v[i], ss);

    // Warp reduce.
#pragma unroll
    for (int o = 16; o > 0; o >>= 1) ss += __shfl_xor_sync(0xffffffffu, ss, o);

    // Cross-warp combine (16 warps), single barrier.
    __shared__ float warp_sum[THREADS / 32];
    if ((t & 31) == 0) warp_sum[t >> 5] = ss;
    __syncthreads();

    float tot = 0.0f;
#pragma unroll
    for (int w = 0; w < THREADS / 32; w++) tot += warp_sum[w];

    const float inv = rsqrtf(tot);

    // Scale + one 256-bit streaming store per thread.
    float o8[F_PER_THREAD];
#pragma unroll
    for (int i = 0; i < F_PER_THREAD; i++) o8[i] = v[i] * inv;
    st256_cs(out + off, o8);
}

extern "C" void kernel_launch(void* const* d_in, const int* in_sizes, int n_in,
                              void* d_out, int out_size) {
    const float* in = (const float*)d_in[0];
    float* out = (float*)d_out;
    l2norm_row256b_kernel<<<ROWS, THREADS>>>(in, out);
}